// round 6
// baseline (speedup 1.0000x reference)
#include <cuda_runtime.h>
#include <cstdint>

#define DIAM   1024
#define NPIX   (DIAM * DIAM)
#define N_WL   31
#define NEL    (NPIX * N_WL)        // 32,505,856
#define VEC    8
#define NTH    (NEL / VEC)          // 4,063,232 = 15872 * 256 exactly
#define RADIUS 512

// Per-pixel precomputed hmap (table[idx]+noise), or -1.0f for outside-aperture.
// (Inside values are always ~+0.002 > 0, so sign is a free flag.)
__device__ float g_h[NPIX];

__global__ __launch_bounds__(256)
void prepass_kernel(const float* __restrict__ hw,     // height_map_weight [512]
                    const float* __restrict__ noise,  // [NPIX]
                    const float* __restrict__ rad)    // [NPIX]
{
    int i = blockIdx.x * blockDim.x + threadIdx.x;
    if (i >= NPIX) return;

    // q_base_height with exact fp32 rounding (matches reference)
    const float lam0 = 7e-07f;
    float n0 = __fadd_rn(1.5f, __fdiv_rn(4e-15f, __fmul_rn(lam0, lam0)));
    float qh = __fdiv_rn(lam0, __fsub_rn(n0, 1.0f));

    float r = rad[i];
    if (r <= (float)RADIUS) {
        int idx = min(max((int)ceilf(r) - 1, 0), 511);
        float w = hw[idx];                         // 2KB table, L1/L2-hot
        w = fminf(fmaxf(w, -1.0f), 1.0f);
        float normed = __fmul_rn(__fadd_rn(w, 1.0f), 0.5f);
        float tv = __fsub_rn(0.002f, __fmul_rn(qh, normed));
        g_h[i] = __fadd_rn(tv, noise[i]);
    } else {
        g_h[i] = -1.0f;
    }
}

__global__ __launch_bounds__(256)
void doe_main_kernel(const float* __restrict__ fr,   // field_real [NEL]
                     const float* __restrict__ fi,   // field_imag [NEL]
                     const float* __restrict__ wl,   // wavelength [31]
                     float* __restrict__ out)        // [2*NEL]
{
    __shared__ float s_t[N_WL];   // k * delta_n per wavelength
    if (threadIdx.x < N_WL) {
        float l  = wl[threadIdx.x];
        float k  = __fdiv_rn(6.283185307179586f, l);
        float dn = __fsub_rn(__fadd_rn(1.5f, __fdiv_rn(4e-15f, __fmul_rn(l, l))), 1.0f);
        s_t[threadIdx.x] = __fmul_rn(k, dn);
    }
    __syncthreads();

    int q = blockIdx.x * blockDim.x + threadIdx.x;   // exact grid: q < NTH
    int e = q * VEC;
    unsigned p  = (unsigned)e / 31u;
    int      w0 = e - (int)(p * 31u);
    unsigned pB = p + (w0 > (N_WL - VEC));           // span crosses pixel boundary

    float hA = g_h[p];
    float hB = g_h[pB];

    float4* oR = (float4*)(out + e);
    float4* oI = (float4*)(out + NEL + e);

    if (hA < 0.0f && hB < 0.0f) {
        float4 z = make_float4(0.f, 0.f, 0.f, 0.f);
        oR[0] = z; oR[1] = z; oI[0] = z; oI[1] = z;
        return;
    }

    const float4* fr4 = (const float4*)(fr + e);
    const float4* fi4 = (const float4*)(fi + e);
    float4 fra = fr4[0], frb = fr4[1];   // front-batched loads: MLP
    float4 fia = fi4[0], fib = fi4[1];

    float fv[8] = {fra.x, fra.y, fra.z, fra.w, frb.x, frb.y, frb.z, frb.w};
    float gv[8] = {fia.x, fia.y, fia.z, fia.w, fib.x, fib.y, fib.z, fib.w};
    float ov[8], wv[8];

    bool inA = (hA >= 0.0f);
    bool inB = (hB >= 0.0f);

    #pragma unroll
    for (int k = 0; k < VEC; k++) {
        int  wli    = w0 + k;
        bool second = (wli >= N_WL);
        int  wlm    = second ? wli - N_WL : wli;
        float h     = second ? hB : hA;
        bool  in    = second ? inB : inA;

        float ph = __fmul_rn(s_t[wlm], h);
        // 2-step Cody-Waite reduction to |r| <= pi/4 (fp32-exact vs reference phase)
        float j  = rintf(__fmul_rn(ph, 0.63661977236758134f));
        float r  = fmaf(j, -1.5707963705062866e+00f, ph);
        r        = fmaf(j,  4.3711390001862449e-08f, r);
        int  qi  = (int)j;
        // Hardware sincos on the reduced argument (RRO + 2x MUFU, ~3.6e-7 abs err)
        float sr, cr;
        __sincosf(r, &sr, &cr);
        bool odd = (qi & 1);
        float s = odd ? cr : sr;
        float c = odd ? sr : cr;
        s = (qi & 2)       ? -s : s;
        c = ((qi + 1) & 2) ? -c : c;

        float o_r = __fsub_rn(__fmul_rn(fv[k], c), __fmul_rn(gv[k], s));
        float o_i = __fadd_rn(__fmul_rn(fv[k], s), __fmul_rn(gv[k], c));
        ov[k] = in ? o_r : 0.0f;
        wv[k] = in ? o_i : 0.0f;
    }

    oR[0] = make_float4(ov[0], ov[1], ov[2], ov[3]);
    oR[1] = make_float4(ov[4], ov[5], ov[6], ov[7]);
    oI[0] = make_float4(wv[0], wv[1], wv[2], wv[3]);
    oI[1] = make_float4(wv[4], wv[5], wv[6], wv[7]);
}

extern "C" void kernel_launch(void* const* d_in, const int* in_sizes, int n_in,
                              void* d_out, int out_size) {
    const float* hw    = (const float*)d_in[0];  // height_map_weight
    const float* fr    = (const float*)d_in[1];  // field_real
    const float* fi    = (const float*)d_in[2];  // field_imag
    const float* wl    = (const float*)d_in[3];  // wavelength
    const float* noise = (const float*)d_in[4];  // noise
    const float* rad   = (const float*)d_in[5];  // radius_distance
    // d_in[6] aperture == (rad <= 512), folded into g_h sign

    prepass_kernel<<<NPIX / 256, 256>>>(hw, noise, rad);
    doe_main_kernel<<<NTH / 256, 256>>>(fr, fi, wl, (float*)d_out);
}

// round 9
// speedup vs baseline: 1.1421x; 1.1421x over previous
#include <cuda_runtime.h>
#include <cstdint>

#define DIAM   1024
#define NPIX   (DIAM * DIAM)
#define N_WL   31
#define NEL    (NPIX * N_WL)        // 32,505,856
#define VEC    8
#define NTH    (NEL / VEC)          // 4,063,232 = 15872 * 256 exactly
#define RADIUS 512

__global__ __launch_bounds__(256)
void doe_kernel(const float* __restrict__ hw,     // height_map_weight [512]
                const float* __restrict__ fr,     // field_real [NEL]
                const float* __restrict__ fi,     // field_imag [NEL]
                const float* __restrict__ wl,     // wavelength [31]
                const float* __restrict__ noise,  // [NPIX]
                const float* __restrict__ rad,    // radius_distance [NPIX]
                float* __restrict__ out)          // [2*NEL]
{
    __shared__ float s_t[N_WL];   // k * delta_n per wavelength
    if (threadIdx.x < N_WL) {
        float l  = wl[threadIdx.x];
        float k  = __fdiv_rn(6.283185307179586f, l);
        float dn = __fsub_rn(__fadd_rn(1.5f, __fdiv_rn(4e-15f, __fmul_rn(l, l))), 1.0f);
        s_t[threadIdx.x] = __fmul_rn(k, dn);
    }
    __syncthreads();

    int q = blockIdx.x * blockDim.x + threadIdx.x;   // exact grid: q < NTH
    int e = q * VEC;
    unsigned p  = (unsigned)e / 31u;
    int      w0 = e - (int)(p * 31u);
    unsigned pB = p + (w0 > (N_WL - VEC));           // span may straddle one pixel

    // Ground-truth radius from the input array (quantizer boundaries must
    // match the reference bit-for-bit; do NOT recompute).
    float rA = rad[p];
    float rB = rad[pB];
    bool inA = (rA <= (float)RADIUS);
    bool inB = (rB <= (float)RADIUS);

    float* oR = out + e;
    float* oI = out + NEL + e;

    if (!inA && !inB) {
        float4 z = make_float4(0.f, 0.f, 0.f, 0.f);
        __stcs((float4*)oR,     z);
        __stcs((float4*)oR + 1, z);
        __stcs((float4*)oI,     z);
        __stcs((float4*)oI + 1, z);
        return;
    }

    // Front-batch streaming loads (evict-first: single-touch data)
    float4 fra = __ldcs((const float4*)(fr + e));
    float4 frb = __ldcs((const float4*)(fr + e) + 1);
    float4 fia = __ldcs((const float4*)(fi + e));
    float4 fib = __ldcs((const float4*)(fi + e) + 1);
    float nzA = noise[p];
    float nzB = noise[pB];

    // q_base_height with exact fp32 rounding (constant-folded)
    const float lam0 = 7e-07f;
    float n0 = __fadd_rn(1.5f, __fdiv_rn(4e-15f, __fmul_rn(lam0, lam0)));
    float qh = __fdiv_rn(lam0, __fsub_rn(n0, 1.0f));

    float hA = 0.0f, hB = 0.0f;
    if (inA) {
        int idx = min(max((int)ceilf(rA) - 1, 0), 511);
        float w = fminf(fmaxf(hw[idx], -1.0f), 1.0f);
        float tv = __fsub_rn(0.002f, __fmul_rn(qh, __fmul_rn(__fadd_rn(w, 1.0f), 0.5f)));
        hA = __fadd_rn(tv, nzA);
    }
    if (inB) {
        int idx = min(max((int)ceilf(rB) - 1, 0), 511);
        float w = fminf(fmaxf(hw[idx], -1.0f), 1.0f);
        float tv = __fsub_rn(0.002f, __fmul_rn(qh, __fmul_rn(__fadd_rn(w, 1.0f), 0.5f)));
        hB = __fadd_rn(tv, nzB);
    }

    float fv[8] = {fra.x, fra.y, fra.z, fra.w, frb.x, frb.y, frb.z, frb.w};
    float gv[8] = {fia.x, fia.y, fia.z, fia.w, fib.x, fib.y, fib.z, fib.w};
    float ov[8], wv[8];

    #pragma unroll
    for (int k = 0; k < VEC; k++) {
        int  wli    = w0 + k;
        bool second = (wli >= N_WL);
        int  wlm    = second ? wli - N_WL : wli;
        float h     = second ? hB : hA;
        bool  in    = second ? inB : inA;

        float ph = __fmul_rn(s_t[wlm], h);
        // 2-step Cody-Waite reduction to |r| <= pi/4 (fp32-exact vs reference phase)
        float j  = rintf(__fmul_rn(ph, 0.63661977236758134f));
        float r  = fmaf(j, -1.5707963705062866e+00f, ph);
        r        = fmaf(j,  4.3711390001862449e-08f, r);
        int  qi  = (int)j;
        // Hardware sincos on reduced argument (RRO + 2x MUFU, ~3.6e-7 abs err)
        float sr, cr;
        __sincosf(r, &sr, &cr);
        bool odd = (qi & 1);
        float s = odd ? cr : sr;
        float c = odd ? sr : cr;
        s = (qi & 2)       ? -s : s;
        c = ((qi + 1) & 2) ? -c : c;

        float o_r = __fsub_rn(__fmul_rn(fv[k], c), __fmul_rn(gv[k], s));
        float o_i = __fadd_rn(__fmul_rn(fv[k], s), __fmul_rn(gv[k], c));
        ov[k] = in ? o_r : 0.0f;
        wv[k] = in ? o_i : 0.0f;
    }

    __stcs((float4*)oR,     make_float4(ov[0], ov[1], ov[2], ov[3]));
    __stcs((float4*)oR + 1, make_float4(ov[4], ov[5], ov[6], ov[7]));
    __stcs((float4*)oI,     make_float4(wv[0], wv[1], wv[2], wv[3]));
    __stcs((float4*)oI + 1, make_float4(wv[4], wv[5], wv[6], wv[7]));
}

extern "C" void kernel_launch(void* const* d_in, const int* in_sizes, int n_in,
                              void* d_out, int out_size) {
    const float* hw    = (const float*)d_in[0];  // height_map_weight
    const float* fr    = (const float*)d_in[1];  // field_real
    const float* fi    = (const float*)d_in[2];  // field_imag
    const float* wl    = (const float*)d_in[3];  // wavelength
    const float* noise = (const float*)d_in[4];  // noise
    const float* rad   = (const float*)d_in[5];  // radius_distance
    // d_in[6] aperture == (rad <= 512), recomputed from loaded rad (validated R3/R6)

    doe_kernel<<<NTH / 256, 256>>>(hw, fr, fi, wl, noise, rad, (float*)d_out);
}